// round 9
// baseline (speedup 1.0000x reference)
#include <cuda_runtime.h>
#include <cuda_fp16.h>

#define NN 50000
#define NE 800000
#define DIN 96
#define HID 128
#define NG 256
#define KF 192   // fused K = [x | aggx]

// ---------------- scratch ----------------
__device__ __align__(16) int    g_deg[NN];
__device__ __align__(16) int    g_off[NN + 1];
__device__ __align__(16) int    g_cur[NN];
__device__ __align__(16) int2   g_edge[NE];          // (src, w-as-int)
__device__ __align__(16) __half g_x16[(size_t)NN * DIN];   // fp16 copy of x (gathered)
__device__ __align__(16) float  g_Ax[(size_t)NN * DIN];    // aggx = sum w * x_src (fp32)
__device__ __align__(16) float  g_Wp[KF * HID];  // [W_rel1; W_root1] as [k][j]
__device__ __align__(16) float  g_u[HID];        // W_rel3^T @ W_lin
__device__ __align__(16) float  g_v[HID];        // W_root3^T @ W_lin
__device__            float     g_c;             // W_lin . b3
__device__ __align__(16) float  g_s[NN];         // u . h1_i
__device__ __align__(16) float  g_r[NN];         // v . h1_i
__device__ __align__(16) float  g_z[NN];         // W_lin . h2_i

// ---------------- CSR build ----------------
__global__ void k_count(const int* __restrict__ ei) {
    int e = blockIdx.x * blockDim.x + threadIdx.x;
    if (e < NE) atomicAdd(&g_deg[ei[NE + e]], 1);
}

__global__ void k_scan() {
    __shared__ int wsum[32];
    const int tid = threadIdx.x;
    const int CH = (NN + 1023) / 1024;
    const int base = tid * CH;
    int s = 0;
    for (int i = 0; i < CH; i++) {
        int idx = base + i;
        if (idx < NN) s += g_deg[idx];
    }
    int lane = tid & 31, w = tid >> 5;
    int v = s;
    #pragma unroll
    for (int o = 1; o < 32; o <<= 1) {
        int n = __shfl_up_sync(0xffffffffu, v, o);
        if (lane >= o) v += n;
    }
    if (lane == 31) wsum[w] = v;
    __syncthreads();
    if (w == 0) {
        int x = wsum[lane];
        #pragma unroll
        for (int o = 1; o < 32; o <<= 1) {
            int n = __shfl_up_sync(0xffffffffu, x, o);
            if (lane >= o) x += n;
        }
        wsum[lane] = x;
    }
    __syncthreads();
    int excl = v - s + (w > 0 ? wsum[w - 1] : 0);
    int run = excl;
    for (int i = 0; i < CH; i++) {
        int idx = base + i;
        if (idx < NN) {
            g_off[idx] = run;
            g_cur[idx] = run;
            run += g_deg[idx];
            g_deg[idx] = 0;   // re-zero for next graph replay
        }
    }
    if (tid == 1023) g_off[NN] = run;
}

__global__ void k_scatter(const int* __restrict__ ei, const float* __restrict__ ea) {
    int e = blockIdx.x * blockDim.x + threadIdx.x;
    if (e < NE) {
        int d = ei[NE + e];
        int p = atomicAdd(&g_cur[d], 1);
        g_edge[p] = make_int2(ei[e], __float_as_int(ea[e]));
    }
}

// ---------------- x -> fp16 copy (for edge gathers) ----------------
__global__ void k_conv_x(const float* __restrict__ x) {
    int t = blockIdx.x * blockDim.x + threadIdx.x;
    if (t >= NN * 24) return;
    int row = t / 24;
    int c4 = (t % 24) * 4;
    float4 v = *(const float4*)(x + (size_t)row * DIN + c4);
    __half2 h0 = __floats2half2_rn(v.x, v.y);
    __half2 h1 = __floats2half2_rn(v.z, v.w);
    uint2 o;
    o.x = *(unsigned*)&h0; o.y = *(unsigned*)&h1;
    *(uint2*)(g_x16 + (size_t)row * DIN + c4) = o;
}

// ---------------- weight prep: W' [192][128] + u,v,c ----------------
__global__ void k_prep(const float* __restrict__ Wr1, const float* __restrict__ Wro1,
                       const float* __restrict__ Wr3, const float* __restrict__ Wro3,
                       const float* __restrict__ Wl, const float* __restrict__ b3) {
    if (blockIdx.x < 96) {
        int idx = blockIdx.x * 256 + threadIdx.x;  // covers 192*128 = 24576
        if (idx < KF * HID) {
            int k = idx / HID, j = idx % HID;
            g_Wp[idx] = (k < DIN) ? Wr1[j * DIN + k] : Wro1[j * DIN + (k - DIN)];
        }
    } else {
        int k = threadIdx.x;
        if (k < HID) {
            float su = 0.f, sv = 0.f;
            #pragma unroll 4
            for (int j = 0; j < HID; j++) {
                float wl = Wl[j];
                su = fmaf(wl, Wr3[j * HID + k], su);
                sv = fmaf(wl, Wro3[j * HID + k], sv);
            }
            g_u[k] = su;
            g_v[k] = sv;
            if (k == 0) {
                float c = 0.f;
                for (int j = 0; j < HID; j++) c = fmaf(Wl[j], b3[j], c);
                g_c = c;
            }
        }
    }
}

// ---------------- edge aggregation of raw x: aggx = sum w * x16[src] -----------
// warp per node; lanes 0..23 each own 4 of 96 dims (8B fp16 loads)
__global__ void k_aggx() {
    int node = (blockIdx.x * blockDim.x + threadIdx.x) >> 5;
    if (node >= NN) return;
    int lane = threadIdx.x & 31;
    if (lane >= 24) return;
    int beg = g_off[node], end = g_off[node + 1];
    float ax = 0.f, ay = 0.f, az = 0.f, aw = 0.f;
    float bx = 0.f, by = 0.f, bz = 0.f, bw = 0.f;
    int e = beg;
    for (; e + 1 < end; e += 2) {
        int2 e0 = g_edge[e];
        int2 e1 = g_edge[e + 1];
        uint2 v0 = *(const uint2*)(g_x16 + (size_t)e0.x * DIN + 4 * lane);
        uint2 v1 = *(const uint2*)(g_x16 + (size_t)e1.x * DIN + 4 * lane);
        float w0 = __int_as_float(e0.y);
        float w1 = __int_as_float(e1.y);
        float2 p00 = __half22float2(*(__half2*)&v0.x);
        float2 p01 = __half22float2(*(__half2*)&v0.y);
        float2 p10 = __half22float2(*(__half2*)&v1.x);
        float2 p11 = __half22float2(*(__half2*)&v1.y);
        ax = fmaf(p00.x, w0, ax); ay = fmaf(p00.y, w0, ay);
        az = fmaf(p01.x, w0, az); aw = fmaf(p01.y, w0, aw);
        bx = fmaf(p10.x, w1, bx); by = fmaf(p10.y, w1, by);
        bz = fmaf(p11.x, w1, bz); bw = fmaf(p11.y, w1, bw);
    }
    if (e < end) {
        int2 e0 = g_edge[e];
        uint2 v0 = *(const uint2*)(g_x16 + (size_t)e0.x * DIN + 4 * lane);
        float w0 = __int_as_float(e0.y);
        float2 p00 = __half22float2(*(__half2*)&v0.x);
        float2 p01 = __half22float2(*(__half2*)&v0.y);
        ax = fmaf(p00.x, w0, ax); ay = fmaf(p00.y, w0, ay);
        az = fmaf(p01.x, w0, az); aw = fmaf(p01.y, w0, aw);
    }
    ax += bx; ay += by; az += bz; aw += bw;
    *(float4*)(g_Ax + (size_t)node * DIN + 4 * lane) = make_float4(ax, ay, az, aw);
}

// ---------------- fused GEMM + bias + relu + u/v projection --------------------
// M=NN, N=128, K=192. A row i = [x_i (96) | aggx_i (96)]. Per-tile epilogue
// computes s_i = u.h1_i, r_i = v.h1_i directly (h1 never stored).
__global__ __launch_bounds__(256) void k_gemm_fused(const float* __restrict__ x,
                                                    const float* __restrict__ b1) {
    __shared__ float As[2][16][128];
    __shared__ float Bs[2][16][128];
    const int tid = threadIdx.x;
    const int m0 = blockIdx.x * 128;
    const int ty = tid >> 4, tx = tid & 15;
    const int NI = KF / 16;  // 12

    const int aR0 = tid >> 2, aC0 = (tid & 3) * 4;
    const int bK0 = tid >> 5, bN0 = (tid & 31) * 4;

    float4 pa[2], pb[2];
    auto ldA = [&](int k0) {
        const float* src = (k0 < DIN) ? (x + k0) : (g_Ax + (k0 - DIN));
        #pragma unroll
        for (int i = 0; i < 2; i++) {
            int gr = m0 + aR0 + i * 64;
            pa[i] = (gr < NN) ? *(const float4*)(src + (size_t)gr * DIN + aC0)
                              : make_float4(0.f, 0.f, 0.f, 0.f);
        }
    };
    auto ldB = [&](int k0) {
        #pragma unroll
        for (int i = 0; i < 2; i++) {
            int kk = bK0 + i * 8;
            pb[i] = *(const float4*)(g_Wp + (size_t)(k0 + kk) * HID + bN0);
        }
    };
    auto stAB = [&](int buf) {
        #pragma unroll
        for (int i = 0; i < 2; i++) {
            int r = aR0 + i * 64;
            As[buf][aC0 + 0][r] = pa[i].x;
            As[buf][aC0 + 1][r] = pa[i].y;
            As[buf][aC0 + 2][r] = pa[i].z;
            As[buf][aC0 + 3][r] = pa[i].w;
            *(float4*)&Bs[buf][bK0 + i * 8][bN0] = pb[i];
        }
    };

    float acc[8][8];
    #pragma unroll
    for (int i = 0; i < 8; i++)
        #pragma unroll
        for (int j = 0; j < 8; j++) acc[i][j] = 0.f;

    ldA(0); ldB(0);
    stAB(0);
    __syncthreads();

    int buf = 0;
    for (int it = 0; it < NI; it++) {
        if (it + 1 < NI) { ldA((it + 1) * 16); ldB((it + 1) * 16); }
        #pragma unroll
        for (int k = 0; k < 16; k++) {
            const float4 a0 = *(const float4*)&As[buf][k][ty * 8];
            const float4 a1 = *(const float4*)&As[buf][k][ty * 8 + 4];
            const float4 b0 = *(const float4*)&Bs[buf][k][tx * 8];
            const float4 b1v = *(const float4*)&Bs[buf][k][tx * 8 + 4];
            const float ar[8] = {a0.x, a0.y, a0.z, a0.w, a1.x, a1.y, a1.z, a1.w};
            const float br[8] = {b0.x, b0.y, b0.z, b0.w, b1v.x, b1v.y, b1v.z, b1v.w};
            #pragma unroll
            for (int i = 0; i < 8; i++)
                #pragma unroll
                for (int j = 0; j < 8; j++)
                    acc[i][j] = fmaf(ar[i], br[j], acc[i][j]);
        }
        if (it + 1 < NI) stAB(buf ^ 1);
        __syncthreads();
        buf ^= 1;
    }

    // epilogue: bias + relu + project onto u/v, reduce across tx via smem
    float4 bb0 = *(const float4*)(b1 + tx * 8);
    float4 bb1 = *(const float4*)(b1 + tx * 8 + 4);
    float4 uu0 = *(const float4*)(g_u + tx * 8);
    float4 uu1 = *(const float4*)(g_u + tx * 8 + 4);
    float4 vv0 = *(const float4*)(g_v + tx * 8);
    float4 vv1 = *(const float4*)(g_v + tx * 8 + 4);
    const float bc[8] = {bb0.x, bb0.y, bb0.z, bb0.w, bb1.x, bb1.y, bb1.z, bb1.w};
    const float uc[8] = {uu0.x, uu0.y, uu0.z, uu0.w, uu1.x, uu1.y, uu1.z, uu1.w};
    const float vc[8] = {vv0.x, vv0.y, vv0.z, vv0.w, vv1.x, vv1.y, vv1.z, vv1.w};

    float* sred = (float*)As;  // reuse: 128 rows x 16 tx, s then r (4096 floats)
    #pragma unroll
    for (int i = 0; i < 8; i++) {
        float hs = 0.f, hr = 0.f;
        #pragma unroll
        for (int j = 0; j < 8; j++) {
            float h = fmaxf(acc[i][j] + bc[j], 0.f);
            hs = fmaf(h, uc[j], hs);
            hr = fmaf(h, vc[j], hr);
        }
        sred[(ty * 8 + i) * 16 + tx] = hs;
        sred[2048 + (ty * 8 + i) * 16 + tx] = hr;
    }
    __syncthreads();
    if (tid < 128) {
        int row = m0 + tid;
        if (row < NN) {
            float ss = 0.f, rr = 0.f;
            #pragma unroll
            for (int t = 0; t < 16; t++) {
                ss += sred[tid * 16 + t];
                rr += sred[2048 + tid * 16 + t];
            }
            g_s[row] = ss;
            g_r[row] = rr;
        }
    }
}

// ---------------- layer-2 scalar aggregation: z = sum w*s[src] + r + c ---------
__global__ void k_agg2() {
    int node = blockIdx.x * blockDim.x + threadIdx.x;
    if (node >= NN) return;
    int beg = g_off[node], end = g_off[node + 1];
    float t = 0.f;
    for (int e = beg; e < end; e++) {
        int2 ed = g_edge[e];
        t = fmaf(__int_as_float(ed.y), g_s[ed.x], t);
    }
    g_z[node] = t + g_r[node] + g_c;
}

// ---------------- pooling + head: out = relu(mean(z) + bl) --------------------
__global__ void k_pool(const int* __restrict__ batch, const float* __restrict__ bl,
                       float* __restrict__ out) {
    int g = blockIdx.x;
    int c = threadIdx.x;  // 128
    int lo = 0, hi = NN;
    while (lo < hi) {
        int m = (lo + hi) >> 1;
        if (batch[m] < g) lo = m + 1; else hi = m;
    }
    int l = lo, h = NN;
    while (l < h) {
        int m = (l + h) >> 1;
        if (batch[m] < g + 1) l = m + 1; else h = m;
    }
    int cnt = l - lo;
    float s = 0.f;
    for (int i = lo + c; i < l; i += 128) s += g_z[i];
    __shared__ float red[128];
    red[c] = s;
    __syncthreads();
    for (int st = 64; st > 0; st >>= 1) {
        if (c < st) red[c] += red[c + st];
        __syncthreads();
    }
    if (c == 0) {
        float p = red[0] / fmaxf((float)cnt, 1.f);
        out[g] = fmaxf(p + bl[0], 0.f);
    }
}

// ---------------- launch ----------------
extern "C" void kernel_launch(void* const* d_in, const int* in_sizes, int n_in,
                              void* d_out, int out_size) {
    const float* x     = (const float*)d_in[0];
    const int*   ei    = (const int*)d_in[1];
    const int*   batch = (const int*)d_in[2];
    const float* ea    = (const float*)d_in[3];
    const float* Wr1   = (const float*)d_in[4];
    const float* b1    = (const float*)d_in[5];
    const float* Wro1  = (const float*)d_in[6];
    const float* Wr3   = (const float*)d_in[7];
    const float* b3    = (const float*)d_in[8];
    const float* Wro3  = (const float*)d_in[9];
    const float* Wl    = (const float*)d_in[10];
    const float* bl    = (const float*)d_in[11];
    float* out = (float*)d_out;

    k_count<<<(NE + 255) / 256, 256>>>(ei);
    k_scan<<<1, 1024>>>();
    k_scatter<<<(NE + 255) / 256, 256>>>(ei, ea);
    k_conv_x<<<(NN * 24 + 255) / 256, 256>>>(x);
    k_prep<<<97, 256>>>(Wr1, Wro1, Wr3, Wro3, Wl, b3);

    k_aggx<<<(NN * 32 + 255) / 256, 256>>>();
    k_gemm_fused<<<(NN + 127) / 128, 256>>>(x, b1);
    k_agg2<<<(NN + 255) / 256, 256>>>();
    k_pool<<<NG, 128>>>(batch, bl, out);
}

// round 10
// speedup vs baseline: 1.1017x; 1.1017x over previous
#include <cuda_runtime.h>
#include <cuda_fp16.h>

#define NN 50000
#define NE 800000
#define DIN 96
#define HID 128
#define NG 256
#define NCAT 256   // [W_rel1 | W_root1] concatenated output width

// ---------------- scratch ----------------
__device__ __align__(16) int    g_deg[NN];
__device__ __align__(16) int    g_off[NN + 1];
__device__ __align__(16) int    g_cur[NN];
__device__ __align__(16) int2   g_edge[NE];          // (src, w-as-int)
__device__ __align__(16) float  g_Wc1[DIN * NCAT];
__device__ __align__(16) __half g_Yr16[(size_t)NN * HID];  // rel half, fp16 (gathered)
__device__ __align__(16) float  g_Yroot[(size_t)NN * HID]; // root half, fp32
__device__ __align__(16) float  g_u[HID];   // W_rel3^T @ W_lin
__device__ __align__(16) float  g_v[HID];   // W_root3^T @ W_lin
__device__            float     g_c;        // W_lin . b3
__device__ __align__(16) float  g_s[NN];    // u . h1_i
__device__ __align__(16) float  g_r[NN];    // v . h1_i

// ---------------- fused: degree count + weight prep (independent jobs) --------
#define NB_COUNT ((NE + 255) / 256)   // 3125
#define NB_WP    ((DIN * NCAT + 255) / 256)  // 96
__global__ void k_count_prep(const int* __restrict__ ei,
                             const float* __restrict__ Wr1, const float* __restrict__ Wro1,
                             const float* __restrict__ Wr3, const float* __restrict__ Wro3,
                             const float* __restrict__ Wl, const float* __restrict__ b3) {
    int b = blockIdx.x;
    if (b < NB_COUNT) {
        int e = b * 256 + threadIdx.x;
        if (e < NE) atomicAdd(&g_deg[ei[NE + e]], 1);
    } else if (b < NB_COUNT + NB_WP) {
        int idx = (b - NB_COUNT) * 256 + threadIdx.x;
        if (idx < DIN * NCAT) {
            int k = idx / NCAT, j = idx % NCAT;
            g_Wc1[idx] = (j < HID) ? Wr1[j * DIN + k] : Wro1[(j - HID) * DIN + k];
        }
    } else {
        int k = threadIdx.x;
        if (k < HID) {
            float su = 0.f, sv = 0.f;
            #pragma unroll 4
            for (int j = 0; j < HID; j++) {
                float wl = Wl[j];
                su = fmaf(wl, Wr3[j * HID + k], su);
                sv = fmaf(wl, Wro3[j * HID + k], sv);
            }
            g_u[k] = su;
            g_v[k] = sv;
            if (k == 0) {
                float c = 0.f;
                for (int j = 0; j < HID; j++) c = fmaf(Wl[j], b3[j], c);
                g_c = c;
            }
        }
    }
}

// ---------------- scan (single block; re-zeros g_deg for next replay) ---------
__global__ void k_scan() {
    __shared__ int wsum[32];
    const int tid = threadIdx.x;
    const int CH = (NN + 1023) / 1024;
    const int base = tid * CH;
    int s = 0;
    for (int i = 0; i < CH; i++) {
        int idx = base + i;
        if (idx < NN) s += g_deg[idx];
    }
    int lane = tid & 31, w = tid >> 5;
    int v = s;
    #pragma unroll
    for (int o = 1; o < 32; o <<= 1) {
        int n = __shfl_up_sync(0xffffffffu, v, o);
        if (lane >= o) v += n;
    }
    if (lane == 31) wsum[w] = v;
    __syncthreads();
    if (w == 0) {
        int x = wsum[lane];
        #pragma unroll
        for (int o = 1; o < 32; o <<= 1) {
            int n = __shfl_up_sync(0xffffffffu, x, o);
            if (lane >= o) x += n;
        }
        wsum[lane] = x;
    }
    __syncthreads();
    int excl = v - s + (w > 0 ? wsum[w - 1] : 0);
    int run = excl;
    for (int i = 0; i < CH; i++) {
        int idx = base + i;
        if (idx < NN) {
            g_off[idx] = run;
            g_cur[idx] = run;
            run += g_deg[idx];
            g_deg[idx] = 0;
        }
    }
    if (tid == 1023) g_off[NN] = run;
}

__global__ void k_scatter(const int* __restrict__ ei, const float* __restrict__ ea) {
    int e = blockIdx.x * blockDim.x + threadIdx.x;
    if (e < NE) {
        int d = ei[NE + e];
        int p = atomicAdd(&g_cur[d], 1);
        g_edge[p] = make_int2(ei[e], __float_as_int(ea[e]));
    }
}

// ---------------- fp32 SGEMM (layer 1): double-buffered, BK=16 ----------------
// blockIdx.x==0 -> rel cols -> g_Yr16 (fp16); ==1 -> root cols -> g_Yroot (fp32)
__global__ __launch_bounds__(256) void k_sgemm(const float* __restrict__ A) {
    const int K = DIN;
    const float* __restrict__ B = g_Wc1;
    __shared__ float As[2][16][128];
    __shared__ float Bs[2][16][128];
    const int tid = threadIdx.x;
    const int m0 = blockIdx.y * 128;
    const int n0 = blockIdx.x * 128;
    const int ty = tid >> 4, tx = tid & 15;
    const int NI = K / 16;

    const int aR0 = tid >> 2, aC0 = (tid & 3) * 4;
    const int bK0 = tid >> 5, bN0 = (tid & 31) * 4;

    float4 pa[2], pb[2];
    auto ldA = [&](int k0) {
        #pragma unroll
        for (int i = 0; i < 2; i++) {
            int gr = m0 + aR0 + i * 64;
            pa[i] = (gr < NN) ? *(const float4*)(A + (size_t)gr * K + k0 + aC0)
                              : make_float4(0.f, 0.f, 0.f, 0.f);
        }
    };
    auto ldB = [&](int k0) {
        #pragma unroll
        for (int i = 0; i < 2; i++) {
            int kk = bK0 + i * 8;
            pb[i] = *(const float4*)(B + (size_t)(k0 + kk) * NCAT + n0 + bN0);
        }
    };
    auto stAB = [&](int buf) {
        #pragma unroll
        for (int i = 0; i < 2; i++) {
            int r = aR0 + i * 64;
            As[buf][aC0 + 0][r] = pa[i].x;
            As[buf][aC0 + 1][r] = pa[i].y;
            As[buf][aC0 + 2][r] = pa[i].z;
            As[buf][aC0 + 3][r] = pa[i].w;
            *(float4*)&Bs[buf][bK0 + i * 8][bN0] = pb[i];
        }
    };

    float acc[8][8];
    #pragma unroll
    for (int i = 0; i < 8; i++)
        #pragma unroll
        for (int j = 0; j < 8; j++) acc[i][j] = 0.f;

    ldA(0); ldB(0);
    stAB(0);
    __syncthreads();

    int buf = 0;
    for (int it = 0; it < NI; it++) {
        if (it + 1 < NI) { ldA((it + 1) * 16); ldB((it + 1) * 16); }
        #pragma unroll
        for (int k = 0; k < 16; k++) {
            const float4 a0 = *(const float4*)&As[buf][k][ty * 8];
            const float4 a1 = *(const float4*)&As[buf][k][ty * 8 + 4];
            const float4 b0 = *(const float4*)&Bs[buf][k][tx * 8];
            const float4 b1 = *(const float4*)&Bs[buf][k][tx * 8 + 4];
            const float ar[8] = {a0.x, a0.y, a0.z, a0.w, a1.x, a1.y, a1.z, a1.w};
            const float br[8] = {b0.x, b0.y, b0.z, b0.w, b1.x, b1.y, b1.z, b1.w};
            #pragma unroll
            for (int i = 0; i < 8; i++)
                #pragma unroll
                for (int j = 0; j < 8; j++)
                    acc[i][j] = fmaf(ar[i], br[j], acc[i][j]);
        }
        if (it + 1 < NI) stAB(buf ^ 1);
        __syncthreads();
        buf ^= 1;
    }

    const bool relPart = (blockIdx.x == 0);
    #pragma unroll
    for (int i = 0; i < 8; i++) {
        int r = m0 + ty * 8 + i;
        if (r >= NN) continue;
        if (relPart) {
            __half2 h0 = __floats2half2_rn(acc[i][0], acc[i][1]);
            __half2 h1 = __floats2half2_rn(acc[i][2], acc[i][3]);
            __half2 h2 = __floats2half2_rn(acc[i][4], acc[i][5]);
            __half2 h3 = __floats2half2_rn(acc[i][6], acc[i][7]);
            uint4 v;
            v.x = *(unsigned*)&h0; v.y = *(unsigned*)&h1;
            v.z = *(unsigned*)&h2; v.w = *(unsigned*)&h3;
            *(uint4*)(g_Yr16 + (size_t)r * HID + tx * 8) = v;
        } else {
            float* d0 = g_Yroot + (size_t)r * HID + tx * 8;
            *(float4*)(d0)     = make_float4(acc[i][0], acc[i][1], acc[i][2], acc[i][3]);
            *(float4*)(d0 + 4) = make_float4(acc[i][4], acc[i][5], acc[i][6], acc[i][7]);
        }
    }
}

// ---------------- layer-1 agg + u/v projection (16 dim-groups x 2 parities) ----
// Lane l: dim-group dg = l&15 (dims 8dg..8dg+7), edge parity par = l>>4.
// One LDG.128 per lane per edge (vs 2x LDG.64 before).
__global__ void k_agg1(const float* __restrict__ bias) {
    int node = (blockIdx.x * blockDim.x + threadIdx.x) >> 5;
    if (node >= NN) return;
    int lane = threadIdx.x & 31;
    int dg = lane & 15;
    int par = lane >> 4;
    int beg = g_off[node], end = g_off[node + 1];
    float acc[8] = {0.f, 0.f, 0.f, 0.f, 0.f, 0.f, 0.f, 0.f};
    for (int e = beg + par; e < end; e += 2) {
        int2 ed = g_edge[e];
        float w = __int_as_float(ed.y);
        uint4 v = *(const uint4*)(g_Yr16 + (size_t)ed.x * HID + 8 * dg);
        float2 q0 = __half22float2(*(__half2*)&v.x);
        float2 q1 = __half22float2(*(__half2*)&v.y);
        float2 q2 = __half22float2(*(__half2*)&v.z);
        float2 q3 = __half22float2(*(__half2*)&v.w);
        acc[0] = fmaf(q0.x, w, acc[0]); acc[1] = fmaf(q0.y, w, acc[1]);
        acc[2] = fmaf(q1.x, w, acc[2]); acc[3] = fmaf(q1.y, w, acc[3]);
        acc[4] = fmaf(q2.x, w, acc[4]); acc[5] = fmaf(q2.y, w, acc[5]);
        acc[6] = fmaf(q3.x, w, acc[6]); acc[7] = fmaf(q3.y, w, acc[7]);
    }
    // combine the two edge-parities (lane <-> lane^16 hold same dims)
    #pragma unroll
    for (int i = 0; i < 8; i++)
        acc[i] += __shfl_xor_sync(0xffffffffu, acc[i], 16);
    // each lane finalizes 4 dims: base = 8*dg + 4*par
    int db = 8 * dg + 4 * par;
    float a0 = acc[4 * par + 0], a1 = acc[4 * par + 1];
    float a2 = acc[4 * par + 2], a3 = acc[4 * par + 3];
    float4 rt = *(const float4*)(g_Yroot + (size_t)node * HID + db);
    float4 bb = *(const float4*)(bias + db);
    float4 uu = *(const float4*)(g_u + db);
    float4 vv = *(const float4*)(g_v + db);
    float h0 = fmaxf(a0 + rt.x + bb.x, 0.f);
    float h1 = fmaxf(a1 + rt.y + bb.y, 0.f);
    float h2 = fmaxf(a2 + rt.z + bb.z, 0.f);
    float h3 = fmaxf(a3 + rt.w + bb.w, 0.f);
    float ps = h0 * uu.x + h1 * uu.y + h2 * uu.z + h3 * uu.w;
    float pr = h0 * vv.x + h1 * vv.y + h2 * vv.z + h3 * vv.w;
    #pragma unroll
    for (int o = 16; o > 0; o >>= 1) {
        ps += __shfl_down_sync(0xffffffffu, ps, o);
        pr += __shfl_down_sync(0xffffffffu, pr, o);
    }
    if (lane == 0) {
        g_s[node] = ps;
        g_r[node] = pr;
    }
}

// ---------------- fused layer-2 scalar agg + pooling + head --------------------
// block per graph (batch sorted): z_i computed inline, reduced, relu'd.
__global__ void k_pool2(const int* __restrict__ batch, const float* __restrict__ bl,
                        float* __restrict__ out) {
    int g = blockIdx.x;
    int c = threadIdx.x;  // 256
    int lo = 0, hi = NN;
    while (lo < hi) {
        int m = (lo + hi) >> 1;
        if (batch[m] < g) lo = m + 1; else hi = m;
    }
    int l = lo, h = NN;
    while (l < h) {
        int m = (l + h) >> 1;
        if (batch[m] < g + 1) l = m + 1; else h = m;
    }
    int cnt = l - lo;
    float sum = 0.f;
    for (int i = lo + c; i < l; i += 256) {
        int beg = g_off[i], end = g_off[i + 1];
        float t = 0.f;
        for (int e = beg; e < end; e++) {
            int2 ed = g_edge[e];
            t = fmaf(__int_as_float(ed.y), g_s[ed.x], t);
        }
        sum += t + g_r[i] + g_c;
    }
    __shared__ float red[256];
    red[c] = sum;
    __syncthreads();
    for (int st = 128; st > 0; st >>= 1) {
        if (c < st) red[c] += red[c + st];
        __syncthreads();
    }
    if (c == 0) {
        float p = red[0] / fmaxf((float)cnt, 1.f);
        out[g] = fmaxf(p + bl[0], 0.f);
    }
}

// ---------------- launch (6 kernels) ----------------
extern "C" void kernel_launch(void* const* d_in, const int* in_sizes, int n_in,
                              void* d_out, int out_size) {
    const float* x     = (const float*)d_in[0];
    const int*   ei    = (const int*)d_in[1];
    const int*   batch = (const int*)d_in[2];
    const float* ea    = (const float*)d_in[3];
    const float* Wr1   = (const float*)d_in[4];
    const float* b1    = (const float*)d_in[5];
    const float* Wro1  = (const float*)d_in[6];
    const float* Wr3   = (const float*)d_in[7];
    const float* b3    = (const float*)d_in[8];
    const float* Wro3  = (const float*)d_in[9];
    const float* Wl    = (const float*)d_in[10];
    const float* bl    = (const float*)d_in[11];
    float* out = (float*)d_out;

    k_count_prep<<<NB_COUNT + NB_WP + 1, 256>>>(ei, Wr1, Wro1, Wr3, Wro3, Wl, b3);
    k_scan<<<1, 1024>>>();
    k_scatter<<<(NE + 255) / 256, 256>>>(ei, ea);

    dim3 ggrid(2, (NN + 127) / 128);
    k_sgemm<<<ggrid, 256>>>(x);
    k_agg1<<<(NN * 32 + 255) / 256, 256>>>(b1);
    k_pool2<<<NG, 256>>>(batch, bl, out);
}

// round 12
// speedup vs baseline: 1.6452x; 1.4933x over previous
#include <cuda_runtime.h>
#include <cuda_fp16.h>

#define NN 50000
#define NE 800000
#define DIN 96
#define HID 128
#define NG 256
#define NCAT 256
#define NNP 53248   // 52 * 1024, padded arrays for vectorized scan

// ---------------- scratch ----------------
__device__ __align__(16) int    g_deg[NNP];      // zero-init; re-zeroed by k_scan
__device__ __align__(16) int    g_off[NNP + 4];  // padded; only [0..NN] meaningful
__device__ __align__(16) int    g_cur[NNP];
__device__ __align__(16) int    g_gs[NG + 1];    // graph start offsets in batch
__device__ __align__(16) int2   g_edge[NE];      // (src, w-as-int)
__device__ __align__(16) float  g_Wc1[DIN * NCAT];
__device__ __align__(16) __half g_Yr16[(size_t)NN * HID];
__device__ __align__(16) float  g_Yroot[(size_t)NN * HID];
__device__ __align__(16) float  g_u[HID];
__device__ __align__(16) float  g_v[HID];
__device__            float     g_c;
__device__ __align__(16) float  g_s[NN];
__device__ __align__(16) float  g_r[NN];

// ---------------- fused: degree count + weight prep + graph bounds ------------
#define NB_COUNT ((NE + 255) / 256)          // 3125
#define NB_WP    ((DIN * NCAT + 255) / 256)  // 96
__global__ void k_count_prep(const int* __restrict__ ei, const int* __restrict__ batch,
                             const float* __restrict__ Wr1, const float* __restrict__ Wro1,
                             const float* __restrict__ Wr3, const float* __restrict__ Wro3,
                             const float* __restrict__ Wl, const float* __restrict__ b3) {
    int b = blockIdx.x;
    if (b < NB_COUNT) {
        int e = b * 256 + threadIdx.x;
        if (e < NE) atomicAdd(&g_deg[ei[NE + e]], 1);
    } else if (b < NB_COUNT + NB_WP) {
        int idx = (b - NB_COUNT) * 256 + threadIdx.x;
        if (idx < DIN * NCAT) {
            int k = idx / NCAT, j = idx % NCAT;
            g_Wc1[idx] = (j < HID) ? Wr1[j * DIN + k] : Wro1[(j - HID) * DIN + k];
        }
    } else if (b == NB_COUNT + NB_WP) {
        int k = threadIdx.x;
        if (k < HID) {
            float su = 0.f, sv = 0.f;
            #pragma unroll 4
            for (int j = 0; j < HID; j++) {
                float wl = Wl[j];
                su = fmaf(wl, Wr3[j * HID + k], su);
                sv = fmaf(wl, Wro3[j * HID + k], sv);
            }
            g_u[k] = su;
            g_v[k] = sv;
            if (k == 0) {
                float c = 0.f;
                for (int j = 0; j < HID; j++) c = fmaf(Wl[j], b3[j], c);
                g_c = c;
            }
        }
    } else {
        // graph bounds: g_gs[g] = lower_bound(batch, g)
        int g = threadIdx.x;  // 0..255
        int lo = 0, hi = NN;
        while (lo < hi) {
            int m = (lo + hi) >> 1;
            if (batch[m] < g) lo = m + 1; else hi = m;
        }
        g_gs[g] = lo;
        if (g == 0) g_gs[NG] = NN;
    }
}

// ---------------- scan: vectorized, two-pass, low register pressure ------------
// Pass 1: sum 52 degrees per thread (int4 loads, values discarded).
// Pass 2: reload (L1/L2 hits), compute running offsets, store off/cur, zero deg.
// Arrays padded to NNP so no bounds checks anywhere; padding degs are 0.
__global__ __launch_bounds__(1024) void k_scan() {
    __shared__ int wsum[32];
    const int tid = threadIdx.x;
    const int base = tid * 52;
    const int4* dp = (const int4*)(g_deg + base);

    int s = 0;
    #pragma unroll
    for (int i = 0; i < 13; i++) {
        int4 d = dp[i];
        s += d.x + d.y + d.z + d.w;
    }

    int lane = tid & 31, w = tid >> 5;
    int v = s;
    #pragma unroll
    for (int o = 1; o < 32; o <<= 1) {
        int n = __shfl_up_sync(0xffffffffu, v, o);
        if (lane >= o) v += n;
    }
    if (lane == 31) wsum[w] = v;
    __syncthreads();
    if (w == 0) {
        int x = wsum[lane];
        #pragma unroll
        for (int o = 1; o < 32; o <<= 1) {
            int n = __shfl_up_sync(0xffffffffu, x, o);
            if (lane >= o) x += n;
        }
        wsum[lane] = x;
    }
    __syncthreads();
    int run = v - s + (w > 0 ? wsum[w - 1] : 0);

    int4* op = (int4*)(g_off + base);
    int4* cp = (int4*)(g_cur + base);
    int4* zp = (int4*)(g_deg + base);
    const int4 z4 = make_int4(0, 0, 0, 0);
    #pragma unroll
    for (int i = 0; i < 13; i++) {
        int4 d = dp[i];      // reload: L1/L2 hit
        int4 o;
        o.x = run; run += d.x;
        o.y = run; run += d.y;
        o.z = run; run += d.z;
        o.w = run; run += d.w;
        op[i] = o;
        cp[i] = o;
        zp[i] = z4;
    }
    if (tid == 0) g_off[NN] = NE;   // overwrite after vector stores (tid covering NN wrote it too, same value since padding degs are 0)
}

__global__ void k_scatter(const int* __restrict__ ei, const float* __restrict__ ea) {
    int e = blockIdx.x * blockDim.x + threadIdx.x;
    if (e < NE) {
        int d = ei[NE + e];
        int p = atomicAdd(&g_cur[d], 1);
        g_edge[p] = make_int2(ei[e], __float_as_int(ea[e]));
    }
}

// ---------------- fp32 SGEMM (layer 1): double-buffered, BK=16 ----------------
__global__ __launch_bounds__(256) void k_sgemm(const float* __restrict__ A) {
    const int K = DIN;
    const float* __restrict__ B = g_Wc1;
    __shared__ float As[2][16][128];
    __shared__ float Bs[2][16][128];
    const int tid = threadIdx.x;
    const int m0 = blockIdx.y * 128;
    const int n0 = blockIdx.x * 128;
    const int ty = tid >> 4, tx = tid & 15;
    const int NI = K / 16;

    const int aR0 = tid >> 2, aC0 = (tid & 3) * 4;
    const int bK0 = tid >> 5, bN0 = (tid & 31) * 4;

    float4 pa[2], pb[2];
    auto ldA = [&](int k0) {
        #pragma unroll
        for (int i = 0; i < 2; i++) {
            int gr = m0 + aR0 + i * 64;
            pa[i] = (gr < NN) ? *(const float4*)(A + (size_t)gr * K + k0 + aC0)
                              : make_float4(0.f, 0.f, 0.f, 0.f);
        }
    };
    auto ldB = [&](int k0) {
        #pragma unroll
        for (int i = 0; i < 2; i++) {
            int kk = bK0 + i * 8;
            pb[i] = *(const float4*)(B + (size_t)(k0 + kk) * NCAT + n0 + bN0);
        }
    };
    auto stAB = [&](int buf) {
        #pragma unroll
        for (int i = 0; i < 2; i++) {
            int r = aR0 + i * 64;
            As[buf][aC0 + 0][r] = pa[i].x;
            As[buf][aC0 + 1][r] = pa[i].y;
            As[buf][aC0 + 2][r] = pa[i].z;
            As[buf][aC0 + 3][r] = pa[i].w;
            *(float4*)&Bs[buf][bK0 + i * 8][bN0] = pb[i];
        }
    };

    float acc[8][8];
    #pragma unroll
    for (int i = 0; i < 8; i++)
        #pragma unroll
        for (int j = 0; j < 8; j++) acc[i][j] = 0.f;

    ldA(0); ldB(0);
    stAB(0);
    __syncthreads();

    int buf = 0;
    for (int it = 0; it < NI; it++) {
        if (it + 1 < NI) { ldA((it + 1) * 16); ldB((it + 1) * 16); }
        #pragma unroll
        for (int k = 0; k < 16; k++) {
            const float4 a0 = *(const float4*)&As[buf][k][ty * 8];
            const float4 a1 = *(const float4*)&As[buf][k][ty * 8 + 4];
            const float4 b0 = *(const float4*)&Bs[buf][k][tx * 8];
            const float4 b1 = *(const float4*)&Bs[buf][k][tx * 8 + 4];
            const float ar[8] = {a0.x, a0.y, a0.z, a0.w, a1.x, a1.y, a1.z, a1.w};
            const float br[8] = {b0.x, b0.y, b0.z, b0.w, b1.x, b1.y, b1.z, b1.w};
            #pragma unroll
            for (int i = 0; i < 8; i++)
                #pragma unroll
                for (int j = 0; j < 8; j++)
                    acc[i][j] = fmaf(ar[i], br[j], acc[i][j]);
        }
        if (it + 1 < NI) stAB(buf ^ 1);
        __syncthreads();
        buf ^= 1;
    }

    const bool relPart = (blockIdx.x == 0);
    #pragma unroll
    for (int i = 0; i < 8; i++) {
        int r = m0 + ty * 8 + i;
        if (r >= NN) continue;
        if (relPart) {
            __half2 h0 = __floats2half2_rn(acc[i][0], acc[i][1]);
            __half2 h1 = __floats2half2_rn(acc[i][2], acc[i][3]);
            __half2 h2 = __floats2half2_rn(acc[i][4], acc[i][5]);
            __half2 h3 = __floats2half2_rn(acc[i][6], acc[i][7]);
            uint4 v;
            v.x = *(unsigned*)&h0; v.y = *(unsigned*)&h1;
            v.z = *(unsigned*)&h2; v.w = *(unsigned*)&h3;
            *(uint4*)(g_Yr16 + (size_t)r * HID + tx * 8) = v;
        } else {
            float* d0 = g_Yroot + (size_t)r * HID + tx * 8;
            *(float4*)(d0)     = make_float4(acc[i][0], acc[i][1], acc[i][2], acc[i][3]);
            *(float4*)(d0 + 4) = make_float4(acc[i][4], acc[i][5], acc[i][6], acc[i][7]);
        }
    }
}

// ---------------- layer-1 agg + u/v projection, 4-edge MLP batches -------------
__global__ void k_agg1(const float* __restrict__ bias) {
    int node = (blockIdx.x * blockDim.x + threadIdx.x) >> 5;
    if (node >= NN) return;
    int lane = threadIdx.x & 31;
    int dg = lane & 15;
    int par = lane >> 4;
    int beg = g_off[node], end = g_off[node + 1];
    float acc[8] = {0.f, 0.f, 0.f, 0.f, 0.f, 0.f, 0.f, 0.f};
    int e = beg + par;
    for (; e + 2 < end; e += 4) {
        int2 ed0 = g_edge[e];
        int2 ed1 = g_edge[e + 2];
        uint4 v0 = *(const uint4*)(g_Yr16 + (size_t)ed0.x * HID + 8 * dg);
        uint4 v1 = *(const uint4*)(g_Yr16 + (size_t)ed1.x * HID + 8 * dg);
        float w0 = __int_as_float(ed0.y);
        float w1 = __int_as_float(ed1.y);
        float2 q0 = __half22float2(*(__half2*)&v0.x);
        float2 q1 = __half22float2(*(__half2*)&v0.y);
        float2 q2 = __half22float2(*(__half2*)&v0.z);
        float2 q3 = __half22float2(*(__half2*)&v0.w);
        acc[0] = fmaf(q0.x, w0, acc[0]); acc[1] = fmaf(q0.y, w0, acc[1]);
        acc[2] = fmaf(q1.x, w0, acc[2]); acc[3] = fmaf(q1.y, w0, acc[3]);
        acc[4] = fmaf(q2.x, w0, acc[4]); acc[5] = fmaf(q2.y, w0, acc[5]);
        acc[6] = fmaf(q3.x, w0, acc[6]); acc[7] = fmaf(q3.y, w0, acc[7]);
        q0 = __half22float2(*(__half2*)&v1.x);
        q1 = __half22float2(*(__half2*)&v1.y);
        q2 = __half22float2(*(__half2*)&v1.z);
        q3 = __half22float2(*(__half2*)&v1.w);
        acc[0] = fmaf(q0.x, w1, acc[0]); acc[1] = fmaf(q0.y, w1, acc[1]);
        acc[2] = fmaf(q1.x, w1, acc[2]); acc[3] = fmaf(q1.y, w1, acc[3]);
        acc[4] = fmaf(q2.x, w1, acc[4]); acc[5] = fmaf(q2.y, w1, acc[5]);
        acc[6] = fmaf(q3.x, w1, acc[6]); acc[7] = fmaf(q3.y, w1, acc[7]);
    }
    if (e < end) {
        int2 ed0 = g_edge[e];
        uint4 v0 = *(const uint4*)(g_Yr16 + (size_t)ed0.x * HID + 8 * dg);
        float w0 = __int_as_float(ed0.y);
        float2 q0 = __half22float2(*(__half2*)&v0.x);
        float2 q1 = __half22float2(*(__half2*)&v0.y);
        float2 q2 = __half22float2(*(__half2*)&v0.z);
        float2 q3 = __half22float2(*(__half2*)&v0.w);
        acc[0] = fmaf(q0.x, w0, acc[0]); acc[1] = fmaf(q0.y, w0, acc[1]);
        acc[2] = fmaf(q1.x, w0, acc[2]); acc[3] = fmaf(q1.y, w0, acc[3]);
        acc[4] = fmaf(q2.x, w0, acc[4]); acc[5] = fmaf(q2.y, w0, acc[5]);
        acc[6] = fmaf(q3.x, w0, acc[6]); acc[7] = fmaf(q3.y, w0, acc[7]);
    }
    #pragma unroll
    for (int i = 0; i < 8; i++)
        acc[i] += __shfl_xor_sync(0xffffffffu, acc[i], 16);
    int db = 8 * dg + 4 * par;
    float a0 = acc[4 * par + 0], a1 = acc[4 * par + 1];
    float a2 = acc[4 * par + 2], a3 = acc[4 * par + 3];
    float4 rt = *(const float4*)(g_Yroot + (size_t)node * HID + db);
    float4 bb = *(const float4*)(bias + db);
    float4 uu = *(const float4*)(g_u + db);
    float4 vv = *(const float4*)(g_v + db);
    float h0 = fmaxf(a0 + rt.x + bb.x, 0.f);
    float h1 = fmaxf(a1 + rt.y + bb.y, 0.f);
    float h2 = fmaxf(a2 + rt.z + bb.z, 0.f);
    float h3 = fmaxf(a3 + rt.w + bb.w, 0.f);
    float ps = h0 * uu.x + h1 * uu.y + h2 * uu.z + h3 * uu.w;
    float pr = h0 * vv.x + h1 * vv.y + h2 * vv.z + h3 * vv.w;
    #pragma unroll
    for (int o = 16; o > 0; o >>= 1) {
        ps += __shfl_down_sync(0xffffffffu, ps, o);
        pr += __shfl_down_sync(0xffffffffu, pr, o);
    }
    if (lane == 0) {
        g_s[node] = ps;
        g_r[node] = pr;
    }
}

// ---------------- fused layer-2 scalar agg + pooling + head --------------------
__global__ void k_pool2(const float* __restrict__ bl, float* __restrict__ out) {
    int g = blockIdx.x;
    int c = threadIdx.x;  // 256
    int lo = g_gs[g], l = g_gs[g + 1];
    int cnt = l - lo;
    float sum = 0.f;
    for (int i = lo + c; i < l; i += 256) {
        int beg = g_off[i], end = g_off[i + 1];
        float t = 0.f;
        int e = beg;
        for (; e + 1 < end; e += 2) {
            int2 ea = g_edge[e];
            int2 eb = g_edge[e + 1];
            float sa = g_s[ea.x];
            float sb = g_s[eb.x];
            t = fmaf(__int_as_float(ea.y), sa, t);
            t = fmaf(__int_as_float(eb.y), sb, t);
        }
        if (e < end) {
            int2 ea = g_edge[e];
            t = fmaf(__int_as_float(ea.y), g_s[ea.x], t);
        }
        sum += t + g_r[i] + g_c;
    }
    __shared__ float red[256];
    red[c] = sum;
    __syncthreads();
    for (int st = 128; st > 0; st >>= 1) {
        if (c < st) red[c] += red[c + st];
        __syncthreads();
    }
    if (c == 0) {
        float p = red[0] / fmaxf((float)cnt, 1.f);
        out[g] = fmaxf(p + bl[0], 0.f);
    }
}

// ---------------- launch ----------------
extern "C" void kernel_launch(void* const* d_in, const int* in_sizes, int n_in,
                              void* d_out, int out_size) {
    const float* x     = (const float*)d_in[0];
    const int*   ei    = (const int*)d_in[1];
    const int*   batch = (const int*)d_in[2];
    const float* ea    = (const float*)d_in[3];
    const float* Wr1   = (const float*)d_in[4];
    const float* b1    = (const float*)d_in[5];
    const float* Wro1  = (const float*)d_in[6];
    const float* Wr3   = (const float*)d_in[7];
    const float* b3    = (const float*)d_in[8];
    const float* Wro3  = (const float*)d_in[9];
    const float* Wl    = (const float*)d_in[10];
    const float* bl    = (const float*)d_in[11];
    float* out = (float*)d_out;

    k_count_prep<<<NB_COUNT + NB_WP + 2, 256>>>(ei, batch, Wr1, Wro1, Wr3, Wro3, Wl, b3);
    k_scan<<<1, 1024>>>();
    k_scatter<<<(NE + 255) / 256, 256>>>(ei, ea);

    dim3 ggrid(2, (NN + 127) / 128);
    k_sgemm<<<ggrid, 256>>>(x);
    k_agg1<<<(NN * 32 + 255) / 256, 256>>>(b1);
    k_pool2<<<NG, 256>>>(bl, out);
}

// round 13
// speedup vs baseline: 1.7741x; 1.0784x over previous
#include <cuda_runtime.h>
#include <cuda_fp16.h>

#define NN 50000
#define NE 800000
#define DIN 96
#define HID 128
#define NG 256
#define NCAT 256
#define NNP 53248   // 52 * 1024, padded arrays for vectorized scan

// ---------------- scratch ----------------
__device__ __align__(16) int    g_deg[NNP];      // zero-init; re-zeroed by k_scan
__device__ __align__(16) int    g_off[NNP + 4];
__device__ __align__(16) int    g_cur[NNP];
__device__ __align__(16) int    g_gs[NG + 1];
__device__ __align__(16) int2   g_edge[NE];
__device__ __align__(16) float  g_Wc1[DIN * NCAT];
__device__ __align__(16) __half g_Yr16[(size_t)NN * HID];
__device__ __align__(16) float  g_Yroot[(size_t)NN * HID];
__device__ __align__(16) float  g_u[HID];
__device__ __align__(16) float  g_v[HID];
__device__            float     g_c;
__device__ __align__(16) float  g_s[NN];
__device__ __align__(16) float  g_r[NN];

// ---------------- fused: degree count + weight prep + graph bounds ------------
#define NB_COUNT ((NE + 255) / 256)          // 3125
#define NB_WP    ((DIN * NCAT + 255) / 256)  // 96
__global__ void k_count_prep(const int* __restrict__ ei, const int* __restrict__ batch,
                             const float* __restrict__ Wr1, const float* __restrict__ Wro1,
                             const float* __restrict__ Wr3, const float* __restrict__ Wro3,
                             const float* __restrict__ Wl, const float* __restrict__ b3) {
    int b = blockIdx.x;
    if (b < NB_COUNT) {
        int e = b * 256 + threadIdx.x;
        if (e < NE) atomicAdd(&g_deg[ei[NE + e]], 1);
    } else if (b < NB_COUNT + NB_WP) {
        int idx = (b - NB_COUNT) * 256 + threadIdx.x;
        if (idx < DIN * NCAT) {
            int k = idx / NCAT, j = idx % NCAT;
            g_Wc1[idx] = (j < HID) ? Wr1[j * DIN + k] : Wro1[(j - HID) * DIN + k];
        }
    } else if (b == NB_COUNT + NB_WP) {
        int k = threadIdx.x;
        if (k < HID) {
            float su = 0.f, sv = 0.f;
            #pragma unroll 4
            for (int j = 0; j < HID; j++) {
                float wl = Wl[j];
                su = fmaf(wl, Wr3[j * HID + k], su);
                sv = fmaf(wl, Wro3[j * HID + k], sv);
            }
            g_u[k] = su;
            g_v[k] = sv;
            if (k == 0) {
                float c = 0.f;
                for (int j = 0; j < HID; j++) c = fmaf(Wl[j], b3[j], c);
                g_c = c;
            }
        }
    } else {
        int g = threadIdx.x;  // 0..255
        int lo = 0, hi = NN;
        while (lo < hi) {
            int m = (lo + hi) >> 1;
            if (batch[m] < g) lo = m + 1; else hi = m;
        }
        g_gs[g] = lo;
        if (g == 0) g_gs[NG] = NN;
    }
}

// ---------------- scan: vectorized, two-pass ----------------
__global__ __launch_bounds__(1024) void k_scan() {
    __shared__ int wsum[32];
    const int tid = threadIdx.x;
    const int base = tid * 52;
    const int4* dp = (const int4*)(g_deg + base);

    int s = 0;
    #pragma unroll
    for (int i = 0; i < 13; i++) {
        int4 d = dp[i];
        s += d.x + d.y + d.z + d.w;
    }

    int lane = tid & 31, w = tid >> 5;
    int v = s;
    #pragma unroll
    for (int o = 1; o < 32; o <<= 1) {
        int n = __shfl_up_sync(0xffffffffu, v, o);
        if (lane >= o) v += n;
    }
    if (lane == 31) wsum[w] = v;
    __syncthreads();
    if (w == 0) {
        int x = wsum[lane];
        #pragma unroll
        for (int o = 1; o < 32; o <<= 1) {
            int n = __shfl_up_sync(0xffffffffu, x, o);
            if (lane >= o) x += n;
        }
        wsum[lane] = x;
    }
    __syncthreads();
    int run = v - s + (w > 0 ? wsum[w - 1] : 0);

    int4* op = (int4*)(g_off + base);
    int4* cp = (int4*)(g_cur + base);
    int4* zp = (int4*)(g_deg + base);
    const int4 z4 = make_int4(0, 0, 0, 0);
    #pragma unroll
    for (int i = 0; i < 13; i++) {
        int4 d = dp[i];
        int4 o;
        o.x = run; run += d.x;
        o.y = run; run += d.y;
        o.z = run; run += d.z;
        o.w = run; run += d.w;
        op[i] = o;
        cp[i] = o;
        zp[i] = z4;
    }
    if (tid == 0) g_off[NN] = NE;
}

// ---------------- fused: SGEMM (blocks 0..781) + scatter (rest) ---------------
#define NB_GEMM (2 * ((NN + 127) / 128))   // 782
__global__ __launch_bounds__(256) void k_gemm_scatter(const float* __restrict__ A,
                                                      const int* __restrict__ ei,
                                                      const float* __restrict__ ea) {
    __shared__ float As[2][16][128];
    __shared__ float Bs[2][16][128];
    const int bid = blockIdx.x;
    const int tid = threadIdx.x;

    if (bid >= NB_GEMM) {
        // -------- scatter part --------
        int e = (bid - NB_GEMM) * 256 + tid;
        if (e < NE) {
            int d = ei[NE + e];
            int p = atomicAdd(&g_cur[d], 1);
            g_edge[p] = make_int2(ei[e], __float_as_int(ea[e]));
        }
        return;
    }

    // -------- GEMM part --------
    const int K = DIN;
    const float* __restrict__ B = g_Wc1;
    const int m0 = (bid >> 1) * 128;
    const int n0 = (bid & 1) * 128;
    const int ty = tid >> 4, tx = tid & 15;
    const int NI = K / 16;

    const int aR0 = tid >> 2, aC0 = (tid & 3) * 4;
    const int bK0 = tid >> 5, bN0 = (tid & 31) * 4;

    float4 pa[2], pb[2];
    auto ldA = [&](int k0) {
        #pragma unroll
        for (int i = 0; i < 2; i++) {
            int gr = m0 + aR0 + i * 64;
            pa[i] = (gr < NN) ? *(const float4*)(A + (size_t)gr * K + k0 + aC0)
                              : make_float4(0.f, 0.f, 0.f, 0.f);
        }
    };
    auto ldB = [&](int k0) {
        #pragma unroll
        for (int i = 0; i < 2; i++) {
            int kk = bK0 + i * 8;
            pb[i] = *(const float4*)(B + (size_t)(k0 + kk) * NCAT + n0 + bN0);
        }
    };
    auto stAB = [&](int buf) {
        #pragma unroll
        for (int i = 0; i < 2; i++) {
            int r = aR0 + i * 64;
            As[buf][aC0 + 0][r] = pa[i].x;
            As[buf][aC0 + 1][r] = pa[i].y;
            As[buf][aC0 + 2][r] = pa[i].z;
            As[buf][aC0 + 3][r] = pa[i].w;
            *(float4*)&Bs[buf][bK0 + i * 8][bN0] = pb[i];
        }
    };

    float acc[8][8];
    #pragma unroll
    for (int i = 0; i < 8; i++)
        #pragma unroll
        for (int j = 0; j < 8; j++) acc[i][j] = 0.f;

    ldA(0); ldB(0);
    stAB(0);
    __syncthreads();

    int buf = 0;
    for (int it = 0; it < NI; it++) {
        if (it + 1 < NI) { ldA((it + 1) * 16); ldB((it + 1) * 16); }
        #pragma unroll
        for (int k = 0; k < 16; k++) {
            const float4 a0 = *(const float4*)&As[buf][k][ty * 8];
            const float4 a1 = *(const float4*)&As[buf][k][ty * 8 + 4];
            const float4 b0 = *(const float4*)&Bs[buf][k][tx * 8];
            const float4 b1 = *(const float4*)&Bs[buf][k][tx * 8 + 4];
            const float ar[8] = {a0.x, a0.y, a0.z, a0.w, a1.x, a1.y, a1.z, a1.w};
            const float br[8] = {b0.x, b0.y, b0.z, b0.w, b1.x, b1.y, b1.z, b1.w};
            #pragma unroll
            for (int i = 0; i < 8; i++)
                #pragma unroll
                for (int j = 0; j < 8; j++)
                    acc[i][j] = fmaf(ar[i], br[j], acc[i][j]);
        }
        if (it + 1 < NI) stAB(buf ^ 1);
        __syncthreads();
        buf ^= 1;
    }

    const bool relPart = ((bid & 1) == 0);
    #pragma unroll
    for (int i = 0; i < 8; i++) {
        int r = m0 + ty * 8 + i;
        if (r >= NN) continue;
        if (relPart) {
            __half2 h0 = __floats2half2_rn(acc[i][0], acc[i][1]);
            __half2 h1 = __floats2half2_rn(acc[i][2], acc[i][3]);
            __half2 h2 = __floats2half2_rn(acc[i][4], acc[i][5]);
            __half2 h3 = __floats2half2_rn(acc[i][6], acc[i][7]);
            uint4 v;
            v.x = *(unsigned*)&h0; v.y = *(unsigned*)&h1;
            v.z = *(unsigned*)&h2; v.w = *(unsigned*)&h3;
            *(uint4*)(g_Yr16 + (size_t)r * HID + tx * 8) = v;
        } else {
            float* d0 = g_Yroot + (size_t)r * HID + tx * 8;
            *(float4*)(d0)     = make_float4(acc[i][0], acc[i][1], acc[i][2], acc[i][3]);
            *(float4*)(d0 + 4) = make_float4(acc[i][4], acc[i][5], acc[i][6], acc[i][7]);
        }
    }
}

// ---------------- layer-1 agg + u/v projection, MLP-4 batches ------------------
__device__ __forceinline__ void agg_fma(float* acc, uint4 v, float w) {
    float2 q0 = __half22float2(*(__half2*)&v.x);
    float2 q1 = __half22float2(*(__half2*)&v.y);
    float2 q2 = __half22float2(*(__half2*)&v.z);
    float2 q3 = __half22float2(*(__half2*)&v.w);
    acc[0] = fmaf(q0.x, w, acc[0]); acc[1] = fmaf(q0.y, w, acc[1]);
    acc[2] = fmaf(q1.x, w, acc[2]); acc[3] = fmaf(q1.y, w, acc[3]);
    acc[4] = fmaf(q2.x, w, acc[4]); acc[5] = fmaf(q2.y, w, acc[5]);
    acc[6] = fmaf(q3.x, w, acc[6]); acc[7] = fmaf(q3.y, w, acc[7]);
}

__global__ void k_agg1(const float* __restrict__ bias) {
    int node = (blockIdx.x * blockDim.x + threadIdx.x) >> 5;
    if (node >= NN) return;
    int lane = threadIdx.x & 31;
    int dg = lane & 15;
    int par = lane >> 4;
    int beg = g_off[node], end = g_off[node + 1];
    float acc[8] = {0.f, 0.f, 0.f, 0.f, 0.f, 0.f, 0.f, 0.f};
    int e = beg + par;
    // 4 edges per parity in flight (MLP=4)
    for (; e + 6 < end; e += 8) {
        int2 ed0 = g_edge[e];
        int2 ed1 = g_edge[e + 2];
        int2 ed2 = g_edge[e + 4];
        int2 ed3 = g_edge[e + 6];
        uint4 v0 = *(const uint4*)(g_Yr16 + (size_t)ed0.x * HID + 8 * dg);
        uint4 v1 = *(const uint4*)(g_Yr16 + (size_t)ed1.x * HID + 8 * dg);
        uint4 v2 = *(const uint4*)(g_Yr16 + (size_t)ed2.x * HID + 8 * dg);
        uint4 v3 = *(const uint4*)(g_Yr16 + (size_t)ed3.x * HID + 8 * dg);
        agg_fma(acc, v0, __int_as_float(ed0.y));
        agg_fma(acc, v1, __int_as_float(ed1.y));
        agg_fma(acc, v2, __int_as_float(ed2.y));
        agg_fma(acc, v3, __int_as_float(ed3.y));
    }
    for (; e + 2 < end; e += 4) {
        int2 ed0 = g_edge[e];
        int2 ed1 = g_edge[e + 2];
        uint4 v0 = *(const uint4*)(g_Yr16 + (size_t)ed0.x * HID + 8 * dg);
        uint4 v1 = *(const uint4*)(g_Yr16 + (size_t)ed1.x * HID + 8 * dg);
        agg_fma(acc, v0, __int_as_float(ed0.y));
        agg_fma(acc, v1, __int_as_float(ed1.y));
    }
    if (e < end) {
        int2 ed0 = g_edge[e];
        uint4 v0 = *(const uint4*)(g_Yr16 + (size_t)ed0.x * HID + 8 * dg);
        agg_fma(acc, v0, __int_as_float(ed0.y));
    }
    #pragma unroll
    for (int i = 0; i < 8; i++)
        acc[i] += __shfl_xor_sync(0xffffffffu, acc[i], 16);
    int db = 8 * dg + 4 * par;
    float a0 = acc[4 * par + 0], a1 = acc[4 * par + 1];
    float a2 = acc[4 * par + 2], a3 = acc[4 * par + 3];
    float4 rt = *(const float4*)(g_Yroot + (size_t)node * HID + db);
    float4 bb = *(const float4*)(bias + db);
    float4 uu = *(const float4*)(g_u + db);
    float4 vv = *(const float4*)(g_v + db);
    float h0 = fmaxf(a0 + rt.x + bb.x, 0.f);
    float h1 = fmaxf(a1 + rt.y + bb.y, 0.f);
    float h2 = fmaxf(a2 + rt.z + bb.z, 0.f);
    float h3 = fmaxf(a3 + rt.w + bb.w, 0.f);
    float ps = h0 * uu.x + h1 * uu.y + h2 * uu.z + h3 * uu.w;
    float pr = h0 * vv.x + h1 * vv.y + h2 * vv.z + h3 * vv.w;
    #pragma unroll
    for (int o = 16; o > 0; o >>= 1) {
        ps += __shfl_down_sync(0xffffffffu, ps, o);
        pr += __shfl_down_sync(0xffffffffu, pr, o);
    }
    if (lane == 0) {
        g_s[node] = ps;
        g_r[node] = pr;
    }
}

// ---------------- fused layer-2 scalar agg + pooling + head --------------------
__global__ void k_pool2(const float* __restrict__ bl, float* __restrict__ out) {
    int g = blockIdx.x;
    int c = threadIdx.x;  // 256
    int lo = g_gs[g], l = g_gs[g + 1];
    int cnt = l - lo;
    float sum = 0.f;
    for (int i = lo + c; i < l; i += 256) {
        int beg = g_off[i], end = g_off[i + 1];
        float t = 0.f;
        int e = beg;
        for (; e + 1 < end; e += 2) {
            int2 ea = g_edge[e];
            int2 eb = g_edge[e + 1];
            float sa = g_s[ea.x];
            float sb = g_s[eb.x];
            t = fmaf(__int_as_float(ea.y), sa, t);
            t = fmaf(__int_as_float(eb.y), sb, t);
        }
        if (e < end) {
            int2 ea = g_edge[e];
            t = fmaf(__int_as_float(ea.y), g_s[ea.x], t);
        }
        sum += t + g_r[i] + g_c;
    }
    __shared__ float red[256];
    red[c] = sum;
    __syncthreads();
    for (int st = 128; st > 0; st >>= 1) {
        if (c < st) red[c] += red[c + st];
        __syncthreads();
    }
    if (c == 0) {
        float p = red[0] / fmaxf((float)cnt, 1.f);
        out[g] = fmaxf(p + bl[0], 0.f);
    }
}

// ---------------- launch (5 kernels) ----------------
extern "C" void kernel_launch(void* const* d_in, const int* in_sizes, int n_in,
                              void* d_out, int out_size) {
    const float* x     = (const float*)d_in[0];
    const int*   ei    = (const int*)d_in[1];
    const int*   batch = (const int*)d_in[2];
    const float* ea    = (const float*)d_in[3];
    const float* Wr1   = (const float*)d_in[4];
    const float* b1    = (const float*)d_in[5];
    const float* Wro1  = (const float*)d_in[6];
    const float* Wr3   = (const float*)d_in[7];
    const float* b3    = (const float*)d_in[8];
    const float* Wro3  = (const float*)d_in[9];
    const float* Wl    = (const float*)d_in[10];
    const float* bl    = (const float*)d_in[11];
    float* out = (float*)d_out;

    k_count_prep<<<NB_COUNT + NB_WP + 2, 256>>>(ei, batch, Wr1, Wro1, Wr3, Wro3, Wl, b3);
    k_scan<<<1, 1024>>>();
    k_gemm_scatter<<<NB_GEMM + NB_COUNT, 256>>>(x, ei, ea);
    k_agg1<<<(NN * 32 + 255) / 256, 256>>>(b1);
    k_pool2<<<NG, 256>>>(bl, out);
}